// round 2
// baseline (speedup 1.0000x reference)
#include <cuda_runtime.h>
#include <cstdint>

// ---------------------------------------------------------------------------
// GIN block: agg = (1+eps)*x + scatter_add(x[src] -> dst)
//            h1  = agg @ W1^T + b1
//            z   = relu(BN1(h1))         (BN affine folded into GEMM2 load)
//            h2  = z @ W2^T + b2
//            out = relu(BN2(h2))
// N = 50000, D = 128, E = 800000 (sizes taken from in_sizes at runtime)
// ---------------------------------------------------------------------------

#define MAXN 50048  // padded to multiple of 128 rows

__device__ __align__(16) float g_agg[MAXN * 128];
__device__ __align__(16) float g_h1[MAXN * 128];
__device__ float g_stats[512];  // [sum1, sumsq1, sum2, sumsq2] x 128
__device__ float g_ab[512];     // [a1, c1, a2, c2] x 128
__device__ int   g_is64;        // 1 if edge_index is int64, 0 if int32

// ---------------------------------------------------------------------------
// Detect edge_index dtype. If int64 with values < 2^31 (node ids < 50000),
// every odd int32 word (little-endian high half) is zero. For int32 edge data
// the odd words are random node ids — essentially never all zero.
__global__ void detect_kernel(const int* __restrict__ ei32, int E) {
    __shared__ int nz;
    if (threadIdx.x == 0) nz = 0;
    __syncthreads();
    int pairs = E < 2048 ? E : 2048;  // scans < 4096 int32 words, safe either way
    int cnt = 0;
    for (int i = threadIdx.x; i < pairs; i += blockDim.x)
        if (ei32[2 * i + 1] != 0) cnt++;
    if (cnt) atomicOr(&nz, 1);
    __syncthreads();
    if (threadIdx.x == 0) g_is64 = (nz == 0) ? 1 : 0;
}

__global__ void zero_stats_kernel() {
    int t = threadIdx.x;
    if (t < 512) g_stats[t] = 0.f;
}

// agg = (1+eps)*x  (float4 elementwise)
__global__ void init_agg_kernel(const float* __restrict__ x,
                                const float* __restrict__ eps, int n4) {
    int i = blockIdx.x * blockDim.x + threadIdx.x;
    if (i >= n4) return;
    float s = 1.f + eps[0];
    float4 v = ((const float4*)x)[i];
    v.x *= s; v.y *= s; v.z *= s; v.w *= s;
    ((float4*)g_agg)[i] = v;
}

// One warp per edge; each lane handles one float4 (32 x 16B = 512B row).
// Vector reduction atomics (red.global.add.v4.f32, sm_90+) cut atomic count 4x.
__global__ void scatter_kernel(const void* __restrict__ ei,
                               const float* __restrict__ x, int E) {
    long long t = (long long)blockIdx.x * blockDim.x + threadIdx.x;
    int e = (int)(t >> 5);
    if (e >= E) return;
    int lane = (int)(t & 31);
    int src, dst;
    if (g_is64) {
        const long long* p = (const long long*)ei;
        src = (int)p[e];
        dst = (int)p[(long long)E + e];
    } else {
        const int* p = (const int*)ei;
        src = p[e];
        dst = p[E + e];
    }
    float4 v = ((const float4*)(x + (size_t)src * 128))[lane];
    float4* p = ((float4*)(g_agg + (size_t)dst * 128)) + lane;
    asm volatile("red.global.add.v4.f32 [%0], {%1,%2,%3,%4};"
                 :: "l"(p), "f"(v.x), "f"(v.y), "f"(v.z), "f"(v.w)
                 : "memory");
}

// ---------------------------------------------------------------------------
// SGEMM: C[n,j] = sum_k Ain[n,k] * W[j,k] + bias[j]
// Ain[n,k] = A[n,k]                         (ab == nullptr)
//          = relu(A[n,k]*ab[k] + ab[128+k]) (BN1+ReLU folded)
// Block tile 128 rows x 128 cols, BK=32 chunks, 256 threads, 8x8 register tile.
// smem: As[32][132] + Ws[32][132], both stored k-major for broadcast reads.
// ---------------------------------------------------------------------------
__device__ __forceinline__ void gemm_body(const float* __restrict__ A,
                                          const float* __restrict__ W,
                                          const float* __restrict__ bias,
                                          float* __restrict__ C, int N,
                                          const float* __restrict__ ab) {
    __shared__ float As[32][132];
    __shared__ float Ws[32][132];
    int tid = threadIdx.x;
    int m0 = blockIdx.x * 128;
    int ty = tid >> 4;   // 0..15 -> rows ty*8..ty*8+7
    int tx = tid & 15;   // 0..15 -> cols tx*8..tx*8+7

    float acc[8][8];
#pragma unroll
    for (int r = 0; r < 8; ++r)
#pragma unroll
        for (int c = 0; c < 8; ++c) acc[r][c] = 0.f;

    for (int kk = 0; kk < 128; kk += 32) {
        __syncthreads();
#pragma unroll
        for (int p = 0; p < 4; ++p) {
            int i = tid + p * 256;       // 0..1023
            int m = i >> 3;              // 0..127
            int k4 = (i & 7) << 2;       // 0,4,...,28
            int gm = m0 + m;
            if (gm >= N) gm = N - 1;     // clamp (rows never stored)
            float4 v = *(const float4*)(A + (size_t)gm * 128 + kk + k4);
            if (ab) {
                int kg = kk + k4;
                v.x = fmaxf(fmaf(v.x, ab[kg + 0], ab[128 + kg + 0]), 0.f);
                v.y = fmaxf(fmaf(v.y, ab[kg + 1], ab[128 + kg + 1]), 0.f);
                v.z = fmaxf(fmaf(v.z, ab[kg + 2], ab[128 + kg + 2]), 0.f);
                v.w = fmaxf(fmaf(v.w, ab[kg + 3], ab[128 + kg + 3]), 0.f);
            }
            As[k4 + 0][m] = v.x; As[k4 + 1][m] = v.y;
            As[k4 + 2][m] = v.z; As[k4 + 3][m] = v.w;
            // W tile: all 128 rows j=m, ks [kk, kk+32)
            float4 w = *(const float4*)(W + (size_t)m * 128 + kk + k4);
            Ws[k4 + 0][m] = w.x; Ws[k4 + 1][m] = w.y;
            Ws[k4 + 2][m] = w.z; Ws[k4 + 3][m] = w.w;
        }
        __syncthreads();
#pragma unroll 8
        for (int k = 0; k < 32; ++k) {
            float a[8], b[8];
            *(float4*)(a)     = *(const float4*)(&As[k][ty * 8]);
            *(float4*)(a + 4) = *(const float4*)(&As[k][ty * 8 + 4]);
            *(float4*)(b)     = *(const float4*)(&Ws[k][tx * 8]);
            *(float4*)(b + 4) = *(const float4*)(&Ws[k][tx * 8 + 4]);
#pragma unroll
            for (int r = 0; r < 8; ++r)
#pragma unroll
                for (int c = 0; c < 8; ++c)
                    acc[r][c] = fmaf(a[r], b[c], acc[r][c]);
        }
    }

    float bb[8];
    *(float4*)(bb)     = *(const float4*)(bias + tx * 8);
    *(float4*)(bb + 4) = *(const float4*)(bias + tx * 8 + 4);
#pragma unroll
    for (int r = 0; r < 8; ++r) {
        int gm = m0 + ty * 8 + r;
        if (gm < N) {
            float4 o0 = make_float4(acc[r][0] + bb[0], acc[r][1] + bb[1],
                                    acc[r][2] + bb[2], acc[r][3] + bb[3]);
            float4 o1 = make_float4(acc[r][4] + bb[4], acc[r][5] + bb[5],
                                    acc[r][6] + bb[6], acc[r][7] + bb[7]);
            *(float4*)(C + (size_t)gm * 128 + tx * 8)     = o0;
            *(float4*)(C + (size_t)gm * 128 + tx * 8 + 4) = o1;
        }
    }
}

__global__ void __launch_bounds__(256)
gemm1_kernel(const float* __restrict__ W, const float* __restrict__ b, int N) {
    gemm_body(g_agg, W, b, g_h1, N, nullptr);
}

__global__ void __launch_bounds__(256)
gemm2_kernel(const float* __restrict__ W, const float* __restrict__ b,
             float* __restrict__ out, int N) {
    gemm_body(g_h1, W, b, out, N, g_ab);  // a1 at [0..127], c1 at [128..255]
}

// ---------------------------------------------------------------------------
// Column-wise sum / sumsq over N rows. 256 threads: col = tid&127,
// two row-streams per block. Coalesced reads, one atomicAdd per col per block.
// ---------------------------------------------------------------------------
__device__ __forceinline__ void stats_body(const float* __restrict__ H, int N,
                                           float* __restrict__ sum,
                                           float* __restrict__ sumsq) {
    __shared__ float sh[512];
    int tid = threadIdx.x;
    int col = tid & 127;
    int r0 = blockIdx.x * 256 + (tid >> 7);
    int rend = blockIdx.x * 256 + 256;
    if (rend > N) rend = N;
    float s = 0.f, q = 0.f;
    for (int r = r0; r < rend; r += 2) {
        float v = H[(size_t)r * 128 + col];
        s += v;
        q = fmaf(v, v, q);
    }
    sh[tid] = s;
    sh[256 + tid] = q;
    __syncthreads();
    if (tid < 128) {
        atomicAdd(&sum[tid],   sh[tid] + sh[tid + 128]);
        atomicAdd(&sumsq[tid], sh[256 + tid] + sh[256 + tid + 128]);
    }
}

__global__ void stats1_kernel(int N) {
    stats_body(g_h1, N, g_stats, g_stats + 128);
}
__global__ void stats2_kernel(const float* __restrict__ H, int N) {
    stats_body(H, N, g_stats + 256, g_stats + 384);
}

// a = gamma * rsqrt(var + eps); c = beta - mu * a   (biased variance)
__global__ void finalize_kernel(const float* __restrict__ gamma,
                                const float* __restrict__ beta,
                                int statOff, int abOff, float invN) {
    int j = threadIdx.x;  // 128 threads
    float mu  = g_stats[statOff + j] * invN;
    float var = g_stats[statOff + 128 + j] * invN - mu * mu;
    float a = gamma[j] * rsqrtf(var + 1e-5f);
    g_ab[abOff + j] = a;
    g_ab[abOff + 128 + j] = beta[j] - mu * a;
}

// out = relu(out * a2 + c2), in place, float4
__global__ void bnrelu_kernel(float* __restrict__ out, int n4) {
    int i = blockIdx.x * blockDim.x + threadIdx.x;
    if (i >= n4) return;
    int c4 = (i & 31) << 2;
    float4 v = ((float4*)out)[i];
    v.x = fmaxf(fmaf(v.x, g_ab[256 + c4 + 0], g_ab[384 + c4 + 0]), 0.f);
    v.y = fmaxf(fmaf(v.y, g_ab[256 + c4 + 1], g_ab[384 + c4 + 1]), 0.f);
    v.z = fmaxf(fmaf(v.z, g_ab[256 + c4 + 2], g_ab[384 + c4 + 2]), 0.f);
    v.w = fmaxf(fmaf(v.w, g_ab[256 + c4 + 3], g_ab[384 + c4 + 3]), 0.f);
    ((float4*)out)[i] = v;
}

// ---------------------------------------------------------------------------
extern "C" void kernel_launch(void* const* d_in, const int* in_sizes, int n_in,
                              void* d_out, int out_size) {
    const float* x   = (const float*)d_in[0];
    const void*  ei  = d_in[1];
    const float* eps = (const float*)d_in[2];
    const float* W1  = (const float*)d_in[3];
    const float* b1  = (const float*)d_in[4];
    const float* g1  = (const float*)d_in[5];
    const float* be1 = (const float*)d_in[6];
    const float* W2  = (const float*)d_in[7];
    const float* b2  = (const float*)d_in[8];
    const float* g2  = (const float*)d_in[9];
    const float* be2 = (const float*)d_in[10];

    int N = in_sizes[0] / 128;
    int E = in_sizes[1] / 2;
    float* out = (float*)d_out;
    int n4 = N * 32;  // float4 count

    detect_kernel<<<1, 256>>>((const int*)ei, E);
    zero_stats_kernel<<<1, 512>>>();
    init_agg_kernel<<<(n4 + 255) / 256, 256>>>(x, eps, n4);

    long long sthreads = (long long)E * 32;
    scatter_kernel<<<(unsigned)((sthreads + 255) / 256), 256>>>(ei, x, E);

    int gblocks = (N + 127) / 128;
    gemm1_kernel<<<gblocks, 256>>>(W1, b1, N);
    stats1_kernel<<<(N + 255) / 256, 256>>>(N);
    finalize_kernel<<<1, 128>>>(g1, be1, 0, 0, 1.f / (float)N);

    gemm2_kernel<<<gblocks, 256>>>(W2, b2, out, N);
    stats2_kernel<<<(N + 255) / 256, 256>>>(out, N);
    finalize_kernel<<<1, 128>>>(g2, be2, 256, 256, 1.f / (float)N);

    bnrelu_kernel<<<(n4 + 255) / 256, 256>>>(out, n4);
}